// round 12
// baseline (speedup 1.0000x reference)
#include <cuda_runtime.h>

#define B_  2048
#define NL  64
#define NN  16
#define NO  2048
#define ZD  80          // NL + NN
#define MT  16          // rows per GEMM tile
#define MP  8           // row pairs per tile (MT/2)
#define KT  512         // threads per block
#define MAX_TILES 160   // >= max tiles = 128 + 15 = 143
#define NGRID 148       // exactly one CTA per SM -> all resident, safe sw-barrier

// ---- scratch (device globals; no allocation allowed) ----
// 4 pad k-rows so the depth-4 cp.async pipeline may overrun.
__device__ float g_Wg[(NN * NL + 4) * NO];   // 8 MB combined weights, [g][k][col]
__device__ int   g_nid[B_];
__device__ int   g_rows[B_];
__device__ int   g_tile_group[MAX_TILES];
__device__ int   g_tile_rstart[MAX_TILES];
__device__ int   g_tile_rend[MAX_TILES];
__device__ int   g_num_tiles;
__device__ unsigned long long g_bar;   // monotonic ticket barrier (replay-safe)

// ---- packed fp32x2 helpers (Blackwell FFMA2, PTX-only pattern) ----
__device__ __forceinline__ unsigned long long pk2(float a, float b) {
    unsigned long long r;
    asm("mov.b64 %0, {%1, %2};" : "=l"(r) : "f"(a), "f"(b));
    return r;
}
__device__ __forceinline__ void unpk2(unsigned long long u, float& a, float& b) {
    asm("mov.b64 {%0, %1}, %2;" : "=f"(a), "=f"(b) : "l"(u));
}
#define FMA2(acc, a, b) \
    asm("fma.rn.f32x2 %0, %1, %2, %3;" : "=l"(acc) : "l"(a), "l"(b), "l"(acc))

// cp.async 16B: global -> shared, L1-cached
__device__ __forceinline__ void cp16(unsigned smem, const void* g) {
    asm volatile("cp.async.ca.shared.global [%0], [%1], 16;"
                 :: "r"(smem), "l"(g) : "memory");
}
__device__ __forceinline__ void cp_commit() {
    asm volatile("cp.async.commit_group;" ::: "memory");
}
__device__ __forceinline__ void cp_wait3() {
    asm volatile("cp.async.wait_group 3;" ::: "memory");
}

// ============================================================================
// Single persistent kernel, grid = 148 (one CTA per SM, all resident).
// Phase 1: block 0 = prep (argmax/histogram/plan/scatter);
//          blocks 1..147 = Wg[g] = amat_w + amat_site[g] slices.
// Device-wide ticket barrier (monotonic -> safe under graph replay).
// Phase 2: fused [16-row x 2048-col] GEMM (K=64, row-pair FFMA2,
//          depth-4 cp.async W FIFO in smem) + softmax + size_factor.
//          Spare blocks past num_tiles compute theta = exp(px_r).
// ============================================================================
__global__ __launch_bounds__(KT, 1)
void k_fused(const float* __restrict__ z,
             const float* __restrict__ sf,
             const float* __restrict__ amat_w,
             const float* __restrict__ site,
             const float* __restrict__ offsets,
             const float* __restrict__ px_r,
             float* __restrict__ out) {
    const int tid = threadIdx.x;
    const int blk = blockIdx.x;

    // shared: W FIFO (32 KB) + z pairs (4 KB) + reductions (~2 KB)
    __shared__ __align__(16) float4 s_w[4 * KT];
    __shared__ __align__(16) unsigned long long s_z2[NL][MP];  // {z_r0, z_r1}
    __shared__ int   s_row[MT];
    __shared__ float s_red[MT][16];
    __shared__ float s_rowmax[MT];
    __shared__ float s_scale[MT];
    __shared__ int   s_cnt[NN];
    __shared__ int   s_cur[NN];

    // ---------------- Phase 1 ----------------
    if (blk == 0) {
        if (tid < NN) s_cnt[tid] = 0;
        __syncthreads();

        for (int b = tid; b < B_; b += KT) {
            const float* p = z + b * ZD + NL;
            float best = p[0];
            int   bi   = 0;
            #pragma unroll
            for (int j = 1; j < NN; j++) {
                float v = p[j];
                if (v > best) { best = v; bi = j; }  // strict '>' == jnp.argmax
            }
            g_nid[b] = bi;
            atomicAdd(&s_cnt[bi], 1);
        }
        __syncthreads();

        if (tid == 0) {
            int off = 0, t = 0;
            for (int g = 0; g < NN; g++) {
                int c = s_cnt[g];
                s_cur[g] = off;
                int nt = (c + MT - 1) / MT;
                for (int i = 0; i < nt; i++) {
                    g_tile_group[t]  = g;
                    g_tile_rstart[t] = off + i * MT;
                    int e  = off + (i + 1) * MT;
                    int ge = off + c;
                    g_tile_rend[t] = e < ge ? e : ge;
                    t++;
                }
                off += c;
            }
            g_num_tiles = t;
        }
        __syncthreads();

        for (int b = tid; b < B_; b += KT) {
            int pos = atomicAdd(&s_cur[g_nid[b]], 1);
            g_rows[pos] = b;
        }
    } else {
        // Wg build: 524288 float4 across 147 blocks
        const float4* w4 = (const float4*)amat_w;
        const float4* s4 = (const float4*)site;
        float4*       o4 = (float4*)g_Wg;
        const int total = NN * NL * NO / 4;
        for (int idx = (blk - 1) * KT + tid; idx < total; idx += (NGRID - 1) * KT) {
            float4 a = w4[idx & (NL * NO / 4 - 1)];
            float4 b = s4[idx];
            float4 r;
            r.x = a.x + b.x; r.y = a.y + b.y;
            r.z = a.z + b.z; r.w = a.w + b.w;
            o4[idx] = r;
        }
    }

    // ---------------- device-wide barrier (ticket, replay-safe) -------------
    __syncthreads();               // all block stores done before arrive
    if (tid == 0) {
        __threadfence();           // publish phase-1 writes
        unsigned long long ticket = atomicAdd(&g_bar, 1ULL);
        unsigned long long target = (ticket / NGRID + 1ULL) * NGRID;
        while (atomicAdd(&g_bar, 0ULL) < target) { }
    }
    __syncthreads();               // release whole block past the barrier

    // ---------------- Phase 2 ----------------
    const int nt = g_num_tiles;
    if (blk >= nt) {
        // theta: nt <= 143, grid 148 -> >= 5 spares; need NO/KT = 4
        int tb = blk - nt;
        if (tb < NO / KT) {
            int i = tb * KT + tid;
            out[(size_t)B_ * NO + i] = expf(px_r[i]);
        }
        return;
    }

    const int g     = g_tile_group[blk];
    const int rs    = g_tile_rstart[blk];
    const int nrows = g_tile_rend[blk] - rs;

    if (tid < MT) s_row[tid] = (tid < nrows) ? g_rows[rs + tid] : -1;

    // start the W FIFO immediately (overlaps the z fill below)
    const float* Wbase = g_Wg + (size_t)g * (NL * NO) + 4 * tid;
    unsigned s_w_u32 = (unsigned)__cvta_generic_to_shared(s_w);
    #pragma unroll
    for (int p = 0; p < 4; p++) {
        cp16(s_w_u32 + (p * KT + tid) * 16, Wbase + p * NO);
        cp_commit();
    }

    __syncthreads();   // s_row visible for the z fill

    // fill z tile: 16 rows x 64 k, 2 scalars per thread.
    // float view of s_z2: [(k*MP + pair)*2 + half]
    #pragma unroll
    for (int i = tid; i < MT * NL; i += KT) {
        int m = i >> 6, k = i & 63;
        int r = s_row[m];
        float v = (r >= 0) ? z[r * ZD + k] : 0.f;
        ((float*)s_z2)[(k * MP + (m >> 1)) * 2 + (m & 1)] = v;
    }
    __syncthreads();

    // accumulators: acc[pair][col] = {out[2p][c], out[2p+1][c]},
    // initialized with offsets (free epilogue bias).
    float4 of = ((const float4*)offsets)[g * (NO / 4) + tid];
    unsigned long long acc[MP][4];
    {
        unsigned long long o0 = pk2(of.x, of.x), o1 = pk2(of.y, of.y);
        unsigned long long o2 = pk2(of.z, of.z), o3 = pk2(of.w, of.w);
        #pragma unroll
        for (int p = 0; p < MP; p++) {
            acc[p][0] = o0; acc[p][1] = o1; acc[p][2] = o2; acc[p][3] = o3;
        }
    }

    // mainloop: depth-4 self-produced/self-consumed W FIFO (no block syncs)
    #pragma unroll 4
    for (int k = 0; k < NL; k++) {
        cp_wait3();                         // slot k&3 ready (oldest group done)
        float4 w = s_w[(k & 3) * KT + tid]; // private LDS.128, conflict-free
        unsigned long long w0 = pk2(w.x, w.x), w1 = pk2(w.y, w.y);
        unsigned long long w2 = pk2(w.z, w.z), w3 = pk2(w.w, w.w);
        // refill slot with row k+4 (pad rows make overrun safe)
        cp16(s_w_u32 + ((k & 3) * KT + tid) * 16, Wbase + (k + 4) * NO);
        cp_commit();
        // all 8 row-pairs for this k: 4 broadcast LDS.128, zero duplication
        ulonglong2 za = *(const ulonglong2*)&s_z2[k][0];
        ulonglong2 zb = *(const ulonglong2*)&s_z2[k][2];
        ulonglong2 zc = *(const ulonglong2*)&s_z2[k][4];
        ulonglong2 zd = *(const ulonglong2*)&s_z2[k][6];
        FMA2(acc[0][0], za.x, w0); FMA2(acc[0][1], za.x, w1);
        FMA2(acc[0][2], za.x, w2); FMA2(acc[0][3], za.x, w3);
        FMA2(acc[1][0], za.y, w0); FMA2(acc[1][1], za.y, w1);
        FMA2(acc[1][2], za.y, w2); FMA2(acc[1][3], za.y, w3);
        FMA2(acc[2][0], zb.x, w0); FMA2(acc[2][1], zb.x, w1);
        FMA2(acc[2][2], zb.x, w2); FMA2(acc[2][3], zb.x, w3);
        FMA2(acc[3][0], zb.y, w0); FMA2(acc[3][1], zb.y, w1);
        FMA2(acc[3][2], zb.y, w2); FMA2(acc[3][3], zb.y, w3);
        FMA2(acc[4][0], zc.x, w0); FMA2(acc[4][1], zc.x, w1);
        FMA2(acc[4][2], zc.x, w2); FMA2(acc[4][3], zc.x, w3);
        FMA2(acc[5][0], zc.y, w0); FMA2(acc[5][1], zc.y, w1);
        FMA2(acc[5][2], zc.y, w2); FMA2(acc[5][3], zc.y, w3);
        FMA2(acc[6][0], zd.x, w0); FMA2(acc[6][1], zd.x, w1);
        FMA2(acc[6][2], zd.x, w2); FMA2(acc[6][3], zd.x, w3);
        FMA2(acc[7][0], zd.y, w0); FMA2(acc[7][1], zd.y, w1);
        FMA2(acc[7][2], zd.y, w2); FMA2(acc[7][3], zd.y, w3);
    }

    // epilogue: unpack row pairs (offsets folded in), softmax, * size_factor
    float v[MT][4];
    #pragma unroll
    for (int p = 0; p < MP; p++) {
        #pragma unroll
        for (int c = 0; c < 4; c++) {
            float a0, a1;
            unpk2(acc[p][c], a0, a1);      // {row 2p, row 2p+1} for col c
            v[2 * p][c]     = a0;
            v[2 * p + 1][c] = a1;
        }
    }

    const int lane = tid & 31, wrp = tid >> 5;   // 16 warps
    #pragma unroll
    for (int m = 0; m < MT; m++) {
        float lm = fmaxf(fmaxf(v[m][0], v[m][1]), fmaxf(v[m][2], v[m][3]));
        #pragma unroll
        for (int s = 16; s; s >>= 1) lm = fmaxf(lm, __shfl_xor_sync(0xffffffffu, lm, s));
        if (lane == 0) s_red[m][wrp] = lm;
    }
    __syncthreads();
    if (tid < MT) {
        float rm = s_red[tid][0];
        #pragma unroll
        for (int w2 = 1; w2 < 16; w2++) rm = fmaxf(rm, s_red[tid][w2]);
        s_rowmax[tid] = rm;
    }
    __syncthreads();

    #pragma unroll
    for (int m = 0; m < MT; m++) {
        float rm = s_rowmax[m];
        v[m][0] = __expf(v[m][0] - rm);
        v[m][1] = __expf(v[m][1] - rm);
        v[m][2] = __expf(v[m][2] - rm);
        v[m][3] = __expf(v[m][3] - rm);
        float ls = (v[m][0] + v[m][1]) + (v[m][2] + v[m][3]);
        #pragma unroll
        for (int s = 16; s; s >>= 1) ls += __shfl_xor_sync(0xffffffffu, ls, s);
        if (lane == 0) s_red[m][wrp] = ls;
    }
    __syncthreads();
    if (tid < MT) {
        float s = 0.f;
        #pragma unroll
        for (int w2 = 0; w2 < 16; w2++) s += s_red[tid][w2];
        int r = s_row[tid];
        s_scale[tid] = (r >= 0) ? sf[r] / s : 0.f;   // size_factor shape (B,1)
    }
    __syncthreads();

    #pragma unroll
    for (int m = 0; m < MT; m++) {
        int r = s_row[m];
        if (r < 0) continue;
        float sc = s_scale[m];
        float4 o;
        o.x = v[m][0] * sc; o.y = v[m][1] * sc;
        o.z = v[m][2] * sc; o.w = v[m][3] * sc;
        *(float4*)(out + (size_t)r * NO + 4 * tid) = o;   // STG.128 coalesced
    }
}

extern "C" void kernel_launch(void* const* d_in, const int* in_sizes, int n_in,
                              void* d_out, int out_size) {
    const float* z         = (const float*)d_in[0];
    const float* sf        = (const float*)d_in[1];
    const float* amat_w    = (const float*)d_in[2];
    const float* amat_site = (const float*)d_in[3];
    const float* offsets   = (const float*)d_in[4];
    const float* px_r      = (const float*)d_in[5];
    float* out = (float*)d_out;

    k_fused<<<NGRID, KT>>>(z, sf, amat_w, amat_site, offsets, px_r, out);
}

// round 13
// speedup vs baseline: 1.1843x; 1.1843x over previous
#include <cuda_runtime.h>

#define B_  2048
#define NL  64
#define NN  16
#define NO  2048
#define ZD  80          // NL + NN
#define MT  16          // rows per GEMM tile
#define MP  8           // row pairs per tile (MT/2)
#define K5T 512         // threads in GEMM kernel (1 CTA/SM, 128-reg budget)
#define MAX_TILES 160   // >= max tiles = 128 + 15 = 143
#define NWAVE 148

// ---- scratch (device globals; no allocation allowed) ----
// 4 pad k-rows at the end so the 4-deep prefetch ring may overrun.
__device__ float g_Wg[(NN * NL + 4) * NO];   // 8 MB combined weights, [g][k][col]
__device__ int   g_nid[B_];
__device__ int   g_rows[B_];
__device__ int   g_tile_group[MAX_TILES];
__device__ int   g_tile_rstart[MAX_TILES];
__device__ int   g_tile_rend[MAX_TILES];
__device__ int   g_num_tiles;

// ---- packed fp32x2 helpers (Blackwell FFMA2, PTX-only pattern) ----
__device__ __forceinline__ unsigned long long pk2(float a, float b) {
    unsigned long long r;
    asm("mov.b64 %0, {%1, %2};" : "=l"(r) : "f"(a), "f"(b));
    return r;
}
__device__ __forceinline__ void unpk2(unsigned long long u, float& a, float& b) {
    asm("mov.b64 {%0, %1}, %2;" : "=f"(a), "=f"(b) : "l"(u));
}
#define FMA2(acc, a, b) \
    asm("fma.rn.f32x2 %0, %1, %2, %3;" : "=l"(acc) : "l"(a), "l"(b), "l"(acc))

// ============================================================================
// Kernel A: block 0 = prep (vectorized argmax, histogram, tile plan, scatter);
//           blocks 1..NWAVE = Wg[g] = amat_w + amat_site[g] (grid-stride f4).
// ============================================================================
__global__ __launch_bounds__(512)
void kA_prep_wg(const float* __restrict__ z,
                const float* __restrict__ w,
                const float* __restrict__ site) {
    if (blockIdx.x == 0) {
        __shared__ int s_cnt[NN];
        __shared__ int s_cur[NN];
        const int tid = threadIdx.x;

        if (tid < NN) s_cnt[tid] = 0;
        __syncthreads();

        // vectorized argmax: nuisance slice (z + b*80 + 64) is 16B-aligned
        for (int b = tid; b < B_; b += 512) {
            const float4* zn = (const float4*)(z + b * ZD + NL);
            float4 q0 = zn[0], q1 = zn[1], q2 = zn[2], q3 = zn[3];
            float nv[NN] = { q0.x,q0.y,q0.z,q0.w, q1.x,q1.y,q1.z,q1.w,
                             q2.x,q2.y,q2.z,q2.w, q3.x,q3.y,q3.z,q3.w };
            float best = nv[0];
            int   bi   = 0;
            #pragma unroll
            for (int j = 1; j < NN; j++) {
                if (nv[j] > best) { best = nv[j]; bi = j; }  // first-max == jnp.argmax
            }
            g_nid[b] = bi;
            atomicAdd(&s_cnt[bi], 1);
        }
        __syncthreads();

        if (tid == 0) {
            int off = 0, t = 0;
            for (int g = 0; g < NN; g++) {
                int c = s_cnt[g];
                s_cur[g] = off;
                int nt = (c + MT - 1) / MT;
                for (int i = 0; i < nt; i++) {
                    g_tile_group[t]  = g;
                    g_tile_rstart[t] = off + i * MT;
                    int e  = off + (i + 1) * MT;
                    int ge = off + c;
                    g_tile_rend[t] = e < ge ? e : ge;
                    t++;
                }
                off += c;
            }
            g_num_tiles = t;
        }
        __syncthreads();

        for (int b = tid; b < B_; b += 512) {
            int pos = atomicAdd(&s_cur[g_nid[b]], 1);
            g_rows[pos] = b;
        }
    } else {
        const float4* w4 = (const float4*)w;
        const float4* s4 = (const float4*)site;
        float4*       o4 = (float4*)g_Wg;
        const int total = NN * NL * NO / 4;
        for (int idx = (blockIdx.x - 1) * 512 + threadIdx.x;
             idx < total; idx += NWAVE * 512) {
            float4 a = w4[idx & (NL * NO / 4 - 1)];
            float4 b = s4[idx];
            float4 r;
            r.x = a.x + b.x; r.y = a.y + b.y;
            r.z = a.z + b.z; r.w = a.w + b.w;
            o4[idx] = r;
        }
    }
}

// ============================================================================
// Kernel B: fused [16-row x 2048-col] GEMM (K=64) + softmax + scale.
// 512 threads, 4 cols/thread (LDG.128 W), row-pair FFMA2 accumulators
// (acc[pair][col] = {out[2p][c], out[2p+1][c]}), 4-deep W prefetch ring
// (in-flight distance ~264 cyc >= L2 far-die 262 -> LDG latency covered).
// One wave: grid=148 >= 143 tiles; spares compute theta = exp(px_r).
// ============================================================================
__global__ __launch_bounds__(K5T, 1)
void kB_gemm_softmax(const float* __restrict__ z,
                     const float* __restrict__ sf,
                     const float* __restrict__ offsets,
                     const float* __restrict__ px_r,
                     float* __restrict__ out) {
    const int t   = blockIdx.x;
    const int nt  = g_num_tiles;         // uniform, read before any barrier
    const int tid = threadIdx.x;

    if (t >= nt) {
        // theta: nt <= 143, grid = 148 -> >= 5 spares; need NO/512 = 4
        int tb = t - nt;
        if (tb < NO / K5T) {
            int i = tb * K5T + tid;
            out[(size_t)B_ * NO + i] = expf(px_r[i]);
        }
        return;
    }

    const int g   = g_tile_group[t];
    const int rs  = g_tile_rstart[t];
    const int nrows = g_tile_rend[t] - rs;

    __shared__ __align__(16) unsigned long long s_z2[NL][MP]; // {z_r0,z_r1}, 4 KB
    __shared__ int   s_row[MT];
    __shared__ float s_red[MT][16];
    __shared__ float s_rowmax[MT];
    __shared__ float s_scale[MT];

    if (tid < MT) s_row[tid] = (tid < nrows) ? g_rows[rs + tid] : -1;
    __syncthreads();

    // fill z tile: 16 rows x 64 k = 1024 scalars, 2 per thread.
    // float view of s_z2: [(k*MP + pair)*2 + half]
    #pragma unroll
    for (int i = tid; i < MT * NL; i += K5T) {
        int m = i >> 6, k = i & 63;
        int r = s_row[m];
        float v = (r >= 0) ? z[r * ZD + k] : 0.f;
        ((float*)s_z2)[(k * MP + (m >> 1)) * 2 + (m & 1)] = v;
    }
    __syncthreads();

    // thread owns cols 4*tid .. 4*tid+3; acc[pair][col] packed over row pairs,
    // initialized with offsets (folds the epilogue bias add in for free).
    const float4* W4 = (const float4*)g_Wg + (size_t)g * (NL * NO / 4) + tid;
    float4 of = ((const float4*)offsets)[g * (NO / 4) + tid];
    unsigned long long acc[MP][4];
    {
        unsigned long long o0 = pk2(of.x, of.x), o1 = pk2(of.y, of.y);
        unsigned long long o2 = pk2(of.z, of.z), o3 = pk2(of.w, of.w);
        #pragma unroll
        for (int p = 0; p < MP; p++) {
            acc[p][0] = o0; acc[p][1] = o1; acc[p][2] = o2; acc[p][3] = o3;
        }
    }

    // 4-deep software prefetch ring on W (pad rows make k+4 reads safe).
    // unroll 4 renames the rotation -> no register MOVs.
    float4 wr0 = W4[0];
    float4 wr1 = W4[1 * (NO / 4)];
    float4 wr2 = W4[2 * (NO / 4)];
    float4 wr3 = W4[3 * (NO / 4)];

    #pragma unroll 4
    for (int k = 0; k < NL; k++) {
        float4 w = wr0;
        wr0 = wr1; wr1 = wr2; wr2 = wr3;
        wr3 = W4[(k + 4) * (NO / 4)];
        unsigned long long w0 = pk2(w.x, w.x), w1 = pk2(w.y, w.y);
        unsigned long long w2 = pk2(w.z, w.z), w3 = pk2(w.w, w.w);
        // all 8 row-pairs for this k: 4 broadcast LDS.128, zero duplication
        ulonglong2 za = *(const ulonglong2*)&s_z2[k][0];
        ulonglong2 zb = *(const ulonglong2*)&s_z2[k][2];
        ulonglong2 zc = *(const ulonglong2*)&s_z2[k][4];
        ulonglong2 zd = *(const ulonglong2*)&s_z2[k][6];
        FMA2(acc[0][0], za.x, w0); FMA2(acc[0][1], za.x, w1);
        FMA2(acc[0][2], za.x, w2); FMA2(acc[0][3], za.x, w3);
        FMA2(acc[1][0], za.y, w0); FMA2(acc[1][1], za.y, w1);
        FMA2(acc[1][2], za.y, w2); FMA2(acc[1][3], za.y, w3);
        FMA2(acc[2][0], zb.x, w0); FMA2(acc[2][1], zb.x, w1);
        FMA2(acc[2][2], zb.x, w2); FMA2(acc[2][3], zb.x, w3);
        FMA2(acc[3][0], zb.y, w0); FMA2(acc[3][1], zb.y, w1);
        FMA2(acc[3][2], zb.y, w2); FMA2(acc[3][3], zb.y, w3);
        FMA2(acc[4][0], zc.x, w0); FMA2(acc[4][1], zc.x, w1);
        FMA2(acc[4][2], zc.x, w2); FMA2(acc[4][3], zc.x, w3);
        FMA2(acc[5][0], zc.y, w0); FMA2(acc[5][1], zc.y, w1);
        FMA2(acc[5][2], zc.y, w2); FMA2(acc[5][3], zc.y, w3);
        FMA2(acc[6][0], zd.x, w0); FMA2(acc[6][1], zd.x, w1);
        FMA2(acc[6][2], zd.x, w2); FMA2(acc[6][3], zd.x, w3);
        FMA2(acc[7][0], zd.y, w0); FMA2(acc[7][1], zd.y, w1);
        FMA2(acc[7][2], zd.y, w2); FMA2(acc[7][3], zd.y, w3);
    }

    // epilogue: unpack row pairs (offsets already folded in), softmax, * sf
    float v[MT][4];
    #pragma unroll
    for (int p = 0; p < MP; p++) {
        #pragma unroll
        for (int c = 0; c < 4; c++) {
            float a0, a1;
            unpk2(acc[p][c], a0, a1);      // {row 2p, row 2p+1} for col c
            v[2 * p][c]     = a0;
            v[2 * p + 1][c] = a1;
        }
    }

    const int lane = tid & 31, wrp = tid >> 5;   // 16 warps
    #pragma unroll
    for (int m = 0; m < MT; m++) {
        float lm = fmaxf(fmaxf(v[m][0], v[m][1]), fmaxf(v[m][2], v[m][3]));
        #pragma unroll
        for (int s = 16; s; s >>= 1) lm = fmaxf(lm, __shfl_xor_sync(0xffffffffu, lm, s));
        if (lane == 0) s_red[m][wrp] = lm;
    }
    __syncthreads();
    if (tid < MT) {
        float rm = s_red[tid][0];
        #pragma unroll
        for (int w2 = 1; w2 < 16; w2++) rm = fmaxf(rm, s_red[tid][w2]);
        s_rowmax[tid] = rm;
    }
    __syncthreads();

    #pragma unroll
    for (int m = 0; m < MT; m++) {
        float rm = s_rowmax[m];
        v[m][0] = __expf(v[m][0] - rm);
        v[m][1] = __expf(v[m][1] - rm);
        v[m][2] = __expf(v[m][2] - rm);
        v[m][3] = __expf(v[m][3] - rm);
        float ls = (v[m][0] + v[m][1]) + (v[m][2] + v[m][3]);
        #pragma unroll
        for (int s = 16; s; s >>= 1) ls += __shfl_xor_sync(0xffffffffu, ls, s);
        if (lane == 0) s_red[m][wrp] = ls;
    }
    __syncthreads();
    if (tid < MT) {
        float s = 0.f;
        #pragma unroll
        for (int w2 = 0; w2 < 16; w2++) s += s_red[tid][w2];
        int r = s_row[tid];
        s_scale[tid] = (r >= 0) ? sf[r] / s : 0.f;   // size_factor shape (B,1)
    }
    __syncthreads();

    #pragma unroll
    for (int m = 0; m < MT; m++) {
        int r = s_row[m];
        if (r < 0) continue;
        float sc = s_scale[m];
        float4 o;
        o.x = v[m][0] * sc; o.y = v[m][1] * sc;
        o.z = v[m][2] * sc; o.w = v[m][3] * sc;
        *(float4*)(out + (size_t)r * NO + 4 * tid) = o;   // STG.128 coalesced
    }
}

extern "C" void kernel_launch(void* const* d_in, const int* in_sizes, int n_in,
                              void* d_out, int out_size) {
    const float* z         = (const float*)d_in[0];
    const float* sf        = (const float*)d_in[1];
    const float* amat_w    = (const float*)d_in[2];
    const float* amat_site = (const float*)d_in[3];
    const float* offsets   = (const float*)d_in[4];
    const float* px_r      = (const float*)d_in[5];
    float* out = (float*)d_out;

    kA_prep_wg<<<NWAVE + 1, 512>>>(z, amat_w, amat_site);
    kB_gemm_softmax<<<NWAVE, K5T>>>(z, sf, offsets, px_r, out);
}

// round 14
// speedup vs baseline: 1.1923x; 1.0067x over previous
#include <cuda_runtime.h>

#define B_  2048
#define NL  64
#define NN  16
#define NO  2048
#define ZD  80          // NL + NN
#define MT  16          // rows per GEMM tile
#define MP  8           // row pairs per tile (MT/2)
#define K5T 1024        // threads in GEMM kernel (32 warps, 64-reg budget)
#define MAX_TILES 160   // >= max tiles = 128 + 15 = 143
#define NWAVE 148

// ---- scratch (device globals; no allocation allowed) ----
// 2 pad k-rows at the end so the 2-deep prefetch ring may overrun.
__device__ float g_Wg[(NN * NL + 2) * NO];   // 8 MB combined weights, [g][k][col]
__device__ int   g_nid[B_];
__device__ int   g_rows[B_];
__device__ int   g_tile_group[MAX_TILES];
__device__ int   g_tile_rstart[MAX_TILES];
__device__ int   g_tile_rend[MAX_TILES];
__device__ int   g_num_tiles;

// ---- packed fp32x2 helpers (Blackwell FFMA2, PTX-only pattern) ----
__device__ __forceinline__ unsigned long long pk2(float a, float b) {
    unsigned long long r;
    asm("mov.b64 %0, {%1, %2};" : "=l"(r) : "f"(a), "f"(b));
    return r;
}
__device__ __forceinline__ void unpk2(unsigned long long u, float& a, float& b) {
    asm("mov.b64 {%0, %1}, %2;" : "=f"(a), "=f"(b) : "l"(u));
}
#define FMA2(acc, a, b) \
    asm("fma.rn.f32x2 %0, %1, %2, %3;" : "=l"(acc) : "l"(a), "l"(b), "l"(acc))

// ============================================================================
// Kernel A: block 0 = prep (vectorized argmax, histogram, tile plan, scatter);
//           blocks 1..NWAVE = Wg[g] = amat_w + amat_site[g] (grid-stride f4).
// ============================================================================
__global__ __launch_bounds__(512)
void kA_prep_wg(const float* __restrict__ z,
                const float* __restrict__ w,
                const float* __restrict__ site) {
    if (blockIdx.x == 0) {
        __shared__ int s_cnt[NN];
        __shared__ int s_cur[NN];
        const int tid = threadIdx.x;

        if (tid < NN) s_cnt[tid] = 0;
        __syncthreads();

        // vectorized argmax: nuisance slice (z + b*80 + 64) is 16B-aligned
        for (int b = tid; b < B_; b += 512) {
            const float4* zn = (const float4*)(z + b * ZD + NL);
            float4 q0 = zn[0], q1 = zn[1], q2 = zn[2], q3 = zn[3];
            float nv[NN] = { q0.x,q0.y,q0.z,q0.w, q1.x,q1.y,q1.z,q1.w,
                             q2.x,q2.y,q2.z,q2.w, q3.x,q3.y,q3.z,q3.w };
            float best = nv[0];
            int   bi   = 0;
            #pragma unroll
            for (int j = 1; j < NN; j++) {
                if (nv[j] > best) { best = nv[j]; bi = j; }  // first-max == jnp.argmax
            }
            g_nid[b] = bi;
            atomicAdd(&s_cnt[bi], 1);
        }
        __syncthreads();

        if (tid == 0) {
            int off = 0, t = 0;
            for (int g = 0; g < NN; g++) {
                int c = s_cnt[g];
                s_cur[g] = off;
                int nt = (c + MT - 1) / MT;
                for (int i = 0; i < nt; i++) {
                    g_tile_group[t]  = g;
                    g_tile_rstart[t] = off + i * MT;
                    int e  = off + (i + 1) * MT;
                    int ge = off + c;
                    g_tile_rend[t] = e < ge ? e : ge;
                    t++;
                }
                off += c;
            }
            g_num_tiles = t;
        }
        __syncthreads();

        for (int b = tid; b < B_; b += 512) {
            int pos = atomicAdd(&s_cur[g_nid[b]], 1);
            g_rows[pos] = b;
        }
    } else {
        const float4* w4 = (const float4*)w;
        const float4* s4 = (const float4*)site;
        float4*       o4 = (float4*)g_Wg;
        const int total = NN * NL * NO / 4;
        for (int idx = (blockIdx.x - 1) * 512 + threadIdx.x;
             idx < total; idx += NWAVE * 512) {
            float4 a = w4[idx & (NL * NO / 4 - 1)];
            float4 b = s4[idx];
            float4 r;
            r.x = a.x + b.x; r.y = a.y + b.y;
            r.z = a.z + b.z; r.w = a.w + b.w;
            o4[idx] = r;
        }
    }
}

// ============================================================================
// Kernel B: fused [16-row x 2048-col] GEMM (K=64) + softmax + scale.
// 1024 threads, 2 cols/thread, row-pair FFMA2 accumulators (acc = 32 regs
// -> ~60 regs total -> full 32-warp residency, 8 warps/SMSP), 2-deep W
// prefetch ring. One wave: grid=148 >= 143 tiles; spares do theta.
// ============================================================================
__global__ __launch_bounds__(K5T, 1)
void kB_gemm_softmax(const float* __restrict__ z,
                     const float* __restrict__ sf,
                     const float* __restrict__ offsets,
                     const float* __restrict__ px_r,
                     float* __restrict__ out) {
    const int t   = blockIdx.x;
    const int nt  = g_num_tiles;         // uniform, read before any barrier
    const int tid = threadIdx.x;

    if (t >= nt) {
        // theta: nt <= 143, grid = 148 -> >= 5 spares; need NO/1024 = 2
        int tb = t - nt;
        if (tb < NO / K5T) {
            int i = tb * K5T + tid;
            out[(size_t)B_ * NO + i] = expf(px_r[i]);
        }
        return;
    }

    const int g   = g_tile_group[t];
    const int rs  = g_tile_rstart[t];
    const int nrows = g_tile_rend[t] - rs;

    __shared__ __align__(16) unsigned long long s_z2[NL][MP]; // {z_r0,z_r1}, 4 KB
    __shared__ int   s_row[MT];
    __shared__ float s_red[MT][32];
    __shared__ float s_rowmax[MT];
    __shared__ float s_scale[MT];

    if (tid < MT) s_row[tid] = (tid < nrows) ? g_rows[rs + tid] : -1;
    __syncthreads();

    {   // fill z tile: 16 rows x 64 k = 1024 scalars, exactly 1 per thread.
        // float view of s_z2: [(k*MP + pair)*2 + half]
        int m = tid >> 6, k = tid & 63;
        int r = s_row[m];
        float v = (r >= 0) ? z[r * ZD + k] : 0.f;
        ((float*)s_z2)[(k * MP + (m >> 1)) * 2 + (m & 1)] = v;
    }
    __syncthreads();

    // thread owns cols {2*tid, 2*tid+1}; acc[pair][col] packed over row pairs,
    // initialized with offsets (folds the epilogue bias add in for free).
    const float2* W2 = (const float2*)g_Wg + (size_t)g * (NL * NO / 2) + tid;
    float2 of = ((const float2*)offsets)[g * (NO / 2) + tid];
    unsigned long long acc[MP][2];
    {
        unsigned long long o0 = pk2(of.x, of.x), o1 = pk2(of.y, of.y);
        #pragma unroll
        for (int p = 0; p < MP; p++) { acc[p][0] = o0; acc[p][1] = o1; }
    }

    // 2-deep software prefetch ring on W (pad rows make k+2 reads safe)
    float2 wr0 = W2[0];
    float2 wr1 = W2[NO / 2];

    #pragma unroll 4
    for (int k = 0; k < NL; k++) {
        float2 w = wr0;
        wr0 = wr1;
        wr1 = W2[(k + 2) * (NO / 2)];
        unsigned long long w0 = pk2(w.x, w.x), w1 = pk2(w.y, w.y);
        // all 8 row-pairs for this k: 4 broadcast LDS.128, zero duplication
        ulonglong2 za = *(const ulonglong2*)&s_z2[k][0];
        ulonglong2 zb = *(const ulonglong2*)&s_z2[k][2];
        ulonglong2 zc = *(const ulonglong2*)&s_z2[k][4];
        ulonglong2 zd = *(const ulonglong2*)&s_z2[k][6];
        FMA2(acc[0][0], za.x, w0); FMA2(acc[0][1], za.x, w1);
        FMA2(acc[1][0], za.y, w0); FMA2(acc[1][1], za.y, w1);
        FMA2(acc[2][0], zb.x, w0); FMA2(acc[2][1], zb.x, w1);
        FMA2(acc[3][0], zb.y, w0); FMA2(acc[3][1], zb.y, w1);
        FMA2(acc[4][0], zc.x, w0); FMA2(acc[4][1], zc.x, w1);
        FMA2(acc[5][0], zc.y, w0); FMA2(acc[5][1], zc.y, w1);
        FMA2(acc[6][0], zd.x, w0); FMA2(acc[6][1], zd.x, w1);
        FMA2(acc[7][0], zd.y, w0); FMA2(acc[7][1], zd.y, w1);
    }

    // epilogue: unpack row pairs (offsets folded in), softmax over 2048, * sf
    float v[MT][2];
    #pragma unroll
    for (int p = 0; p < MP; p++) {
        float a0, a1;
        unpk2(acc[p][0], a0, a1);          // col0: rows 2p, 2p+1
        v[2 * p][0]     = a0;
        v[2 * p + 1][0] = a1;
        unpk2(acc[p][1], a0, a1);          // col1
        v[2 * p][1]     = a0;
        v[2 * p + 1][1] = a1;
    }

    const int lane = tid & 31, wrp = tid >> 5;   // 32 warps
    #pragma unroll
    for (int m = 0; m < MT; m++) {
        float lm = fmaxf(v[m][0], v[m][1]);
        #pragma unroll
        for (int s = 16; s; s >>= 1) lm = fmaxf(lm, __shfl_xor_sync(0xffffffffu, lm, s));
        if (lane == 0) s_red[m][wrp] = lm;
    }
    __syncthreads();
    if (tid < MT) {
        float rm = s_red[tid][0];
        #pragma unroll
        for (int w2 = 1; w2 < 32; w2++) rm = fmaxf(rm, s_red[tid][w2]);
        s_rowmax[tid] = rm;
    }
    __syncthreads();

    #pragma unroll
    for (int m = 0; m < MT; m++) {
        float rm = s_rowmax[m];
        v[m][0] = __expf(v[m][0] - rm);
        v[m][1] = __expf(v[m][1] - rm);
        float ls = v[m][0] + v[m][1];
        #pragma unroll
        for (int s = 16; s; s >>= 1) ls += __shfl_xor_sync(0xffffffffu, ls, s);
        if (lane == 0) s_red[m][wrp] = ls;
    }
    __syncthreads();
    if (tid < MT) {
        float s = 0.f;
        #pragma unroll
        for (int w2 = 0; w2 < 32; w2++) s += s_red[tid][w2];
        int r = s_row[tid];
        s_scale[tid] = (r >= 0) ? sf[r] / s : 0.f;   // size_factor shape (B,1)
    }
    __syncthreads();

    #pragma unroll
    for (int m = 0; m < MT; m++) {
        int r = s_row[m];
        if (r < 0) continue;
        float sc = s_scale[m];
        float2 o;
        o.x = v[m][0] * sc;
        o.y = v[m][1] * sc;
        *(float2*)(out + (size_t)r * NO + 2 * tid) = o;   // STG.64 coalesced
    }
}

extern "C" void kernel_launch(void* const* d_in, const int* in_sizes, int n_in,
                              void* d_out, int out_size) {
    const float* z         = (const float*)d_in[0];
    const float* sf        = (const float*)d_in[1];
    const float* amat_w    = (const float*)d_in[2];
    const float* amat_site = (const float*)d_in[3];
    const float* offsets   = (const float*)d_in[4];
    const float* px_r      = (const float*)d_in[5];
    float* out = (float*)d_out;

    kA_prep_wg<<<NWAVE + 1, 512>>>(z, amat_w, amat_site);
    kB_gemm_softmax<<<NWAVE, K5T>>>(z, sf, offsets, px_r, out);
}

// round 16
// speedup vs baseline: 1.2098x; 1.0146x over previous
#include <cuda_runtime.h>

#define B_  2048
#define NL  64
#define NN  16
#define NO  2048
#define ZD  80          // NL + NN
#define MT  8           // rows per GEMM tile
#define MP  4           // row pairs per tile (MT/2)
#define K5T 512         // threads in GEMM kernel
#define MAX_TILES 288   // >= max tiles = 256 + 15 = 271
#define NWAVE 148
#define NB_B 280        // >= 271 tiles + 4 theta blocks; 2 CTAs/SM -> one wave

// ---- scratch (device globals; no allocation allowed) ----
// 2 pad k-rows at the end so the 2-deep prefetch ring may overrun.
__device__ float g_Wg[(NN * NL + 2) * NO];   // 8 MB combined weights, [g][k][col]
__device__ int   g_nid[B_];
__device__ int   g_rows[B_];
__device__ int   g_tile_group[MAX_TILES];
__device__ int   g_tile_rstart[MAX_TILES];
__device__ int   g_tile_rend[MAX_TILES];
__device__ int   g_num_tiles;

// ---- packed fp32x2 helpers (Blackwell FFMA2, PTX-only pattern) ----
__device__ __forceinline__ unsigned long long pk2(float a, float b) {
    unsigned long long r;
    asm("mov.b64 %0, {%1, %2};" : "=l"(r) : "f"(a), "f"(b));
    return r;
}
__device__ __forceinline__ void unpk2(unsigned long long u, float& a, float& b) {
    asm("mov.b64 {%0, %1}, %2;" : "=f"(a), "=f"(b) : "l"(u));
}
#define FMA2(acc, a, b) \
    asm("fma.rn.f32x2 %0, %1, %2, %3;" : "=l"(acc) : "l"(a), "l"(b), "l"(acc))

// ============================================================================
// Kernel A: block 0 = prep (vectorized argmax, histogram, tile plan, scatter);
//           blocks 1..NWAVE = Wg[g] = amat_w + amat_site[g] (grid-stride f4).
// ============================================================================
__global__ __launch_bounds__(512)
void kA_prep_wg(const float* __restrict__ z,
                const float* __restrict__ w,
                const float* __restrict__ site) {
    if (blockIdx.x == 0) {
        __shared__ int s_cnt[NN];
        __shared__ int s_cur[NN];
        const int tid = threadIdx.x;

        if (tid < NN) s_cnt[tid] = 0;
        __syncthreads();

        // vectorized argmax: nuisance slice (z + b*80 + 64) is 16B-aligned
        for (int b = tid; b < B_; b += 512) {
            const float4* zn = (const float4*)(z + b * ZD + NL);
            float4 q0 = zn[0], q1 = zn[1], q2 = zn[2], q3 = zn[3];
            float nv[NN] = { q0.x,q0.y,q0.z,q0.w, q1.x,q1.y,q1.z,q1.w,
                             q2.x,q2.y,q2.z,q2.w, q3.x,q3.y,q3.z,q3.w };
            float best = nv[0];
            int   bi   = 0;
            #pragma unroll
            for (int j = 1; j < NN; j++) {
                if (nv[j] > best) { best = nv[j]; bi = j; }  // first-max == jnp.argmax
            }
            g_nid[b] = bi;
            atomicAdd(&s_cnt[bi], 1);
        }
        __syncthreads();

        if (tid == 0) {
            int off = 0, t = 0;
            for (int g = 0; g < NN; g++) {
                int c = s_cnt[g];
                s_cur[g] = off;
                int nt = (c + MT - 1) / MT;
                for (int i = 0; i < nt; i++) {
                    g_tile_group[t]  = g;
                    g_tile_rstart[t] = off + i * MT;
                    int e  = off + (i + 1) * MT;
                    int ge = off + c;
                    g_tile_rend[t] = e < ge ? e : ge;
                    t++;
                }
                off += c;
            }
            g_num_tiles = t;
        }
        __syncthreads();

        for (int b = tid; b < B_; b += 512) {
            int pos = atomicAdd(&s_cur[g_nid[b]], 1);
            g_rows[pos] = b;
        }
    } else {
        const float4* w4 = (const float4*)w;
        const float4* s4 = (const float4*)site;
        float4*       o4 = (float4*)g_Wg;
        const int total = NN * NL * NO / 4;
        for (int idx = (blockIdx.x - 1) * 512 + threadIdx.x;
             idx < total; idx += NWAVE * 512) {
            float4 a = w4[idx & (NL * NO / 4 - 1)];
            float4 b = s4[idx];
            float4 r;
            r.x = a.x + b.x; r.y = a.y + b.y;
            r.z = a.z + b.z; r.w = a.w + b.w;
            o4[idx] = r;
        }
    }
}

// ============================================================================
// Kernel B: fused [8-row x 2048-col] GEMM (K=64) + softmax + scale.
// 512 threads, 4 cols/thread, row-pair FFMA2 accumulators (4 pairs x 4 cols
// = 32 regs), only 2 broadcast LDS.128 per k (balanced LDS:FMA throughput),
// 2-deep W prefetch ring, 2 CTAs/SM -> 32 warps/SM. Spares do theta.
// ============================================================================
__global__ __launch_bounds__(K5T, 2)
void kB_gemm_softmax(const float* __restrict__ z,
                     const float* __restrict__ sf,
                     const float* __restrict__ offsets,
                     const float* __restrict__ px_r,
                     float* __restrict__ out) {
    const int t   = blockIdx.x;
    const int nt  = g_num_tiles;         // uniform, read before any barrier
    const int tid = threadIdx.x;

    if (t >= nt) {
        // theta: nt <= 271, grid = 280 -> >= 9 spares; need NO/512 = 4
        int tb = t - nt;
        if (tb < NO / K5T) {
            int i = tb * K5T + tid;
            out[(size_t)B_ * NO + i] = expf(px_r[i]);
        }
        return;
    }

    const int g   = g_tile_group[t];
    const int rs  = g_tile_rstart[t];
    const int nrows = g_tile_rend[t] - rs;

    __shared__ __align__(16) unsigned long long s_z2[NL][MP]; // {z_r0,z_r1}, 2 KB
    __shared__ int   s_row[MT];
    __shared__ float s_red[MT][16];
    __shared__ float s_rowmax[MT];
    __shared__ float s_scale[MT];

    if (tid < MT) s_row[tid] = (tid < nrows) ? g_rows[rs + tid] : -1;
    __syncthreads();

    {   // fill z tile: 8 rows x 64 k = 512 scalars, exactly 1 per thread.
        // float view of s_z2: [(k*MP + pair)*2 + half]
        int m = tid >> 6, k = tid & 63;
        int r = s_row[m];
        float v = (r >= 0) ? z[r * ZD + k] : 0.f;
        ((float*)s_z2)[(k * MP + (m >> 1)) * 2 + (m & 1)] = v;
    }
    __syncthreads();

    // thread owns cols 4*tid .. 4*tid+3; acc[pair][col] packed over row pairs,
    // initialized with offsets (folds the epilogue bias add in for free).
    const float4* W4 = (const float4*)g_Wg + (size_t)g * (NL * NO / 4) + tid;
    float4 of = ((const float4*)offsets)[g * (NO / 4) + tid];
    unsigned long long acc[MP][4];
    {
        unsigned long long o0 = pk2(of.x, of.x), o1 = pk2(of.y, of.y);
        unsigned long long o2 = pk2(of.z, of.z), o3 = pk2(of.w, of.w);
        #pragma unroll
        for (int p = 0; p < MP; p++) {
            acc[p][0] = o0; acc[p][1] = o1; acc[p][2] = o2; acc[p][3] = o3;
        }
    }

    // 2-deep software prefetch ring on W (pad rows make k+2 reads safe)
    float4 wr0 = W4[0];
    float4 wr1 = W4[NO / 4];

    #pragma unroll 4
    for (int k = 0; k < NL; k++) {
        float4 w = wr0;
        wr0 = wr1;
        wr1 = W4[(k + 2) * (NO / 4)];
        unsigned long long w0 = pk2(w.x, w.x), w1 = pk2(w.y, w.y);
        unsigned long long w2 = pk2(w.z, w.z), w3 = pk2(w.w, w.w);
        // all 4 row-pairs for this k: just 2 broadcast LDS.128
        ulonglong2 za = *(const ulonglong2*)&s_z2[k][0];
        ulonglong2 zb = *(const ulonglong2*)&s_z2[k][2];
        FMA2(acc[0][0], za.x, w0); FMA2(acc[0][1], za.x, w1);
        FMA2(acc[0][2], za.x, w2); FMA2(acc[0][3], za.x, w3);
        FMA2(acc[1][0], za.y, w0); FMA2(acc[1][1], za.y, w1);
        FMA2(acc[1][2], za.y, w2); FMA2(acc[1][3], za.y, w3);
        FMA2(acc[2][0], zb.x, w0); FMA2(acc[2][1], zb.x, w1);
        FMA2(acc[2][2], zb.x, w2); FMA2(acc[2][3], zb.x, w3);
        FMA2(acc[3][0], zb.y, w0); FMA2(acc[3][1], zb.y, w1);
        FMA2(acc[3][2], zb.y, w2); FMA2(acc[3][3], zb.y, w3);
    }

    // epilogue: unpack row pairs (offsets folded in), softmax over 2048, * sf
    float v[MT][4];
    #pragma unroll
    for (int p = 0; p < MP; p++) {
        #pragma unroll
        for (int c = 0; c < 4; c++) {
            float a0, a1;
            unpk2(acc[p][c], a0, a1);      // {row 2p, row 2p+1} for col c
            v[2 * p][c]     = a0;
            v[2 * p + 1][c] = a1;
        }
    }

    const int lane = tid & 31, wrp = tid >> 5;   // 16 warps
    #pragma unroll
    for (int m = 0; m < MT; m++) {
        float lm = fmaxf(fmaxf(v[m][0], v[m][1]), fmaxf(v[m][2], v[m][3]));
        #pragma unroll
        for (int s = 16; s; s >>= 1) lm = fmaxf(lm, __shfl_xor_sync(0xffffffffu, lm, s));
        if (lane == 0) s_red[m][wrp] = lm;
    }
    __syncthreads();
    if (tid < MT) {
        float rm = s_red[tid][0];
        #pragma unroll
        for (int w2 = 1; w2 < 16; w2++) rm = fmaxf(rm, s_red[tid][w2]);
        s_rowmax[tid] = rm;
    }
    __syncthreads();

    #pragma unroll
    for (int m = 0; m < MT; m++) {
        float rm = s_rowmax[m];
        v[m][0] = __expf(v[m][0] - rm);
        v[m][1] = __expf(v[m][1] - rm);
        v[m][2] = __expf(v[m][2] - rm);
        v[m][3] = __expf(v[m][3] - rm);
        float ls = (v[m][0] + v[m][1]) + (v[m][2] + v[m][3]);
        #pragma unroll
        for (int s = 16; s; s >>= 1) ls += __shfl_xor_sync(0xffffffffu, ls, s);
        if (lane == 0) s_red[m][wrp] = ls;
    }
    __syncthreads();
    if (tid < MT) {
        float s = 0.f;
        #pragma unroll
        for (int w2 = 0; w2 < 16; w2++) s += s_red[tid][w2];
        int r = s_row[tid];
        s_scale[tid] = (r >= 0) ? sf[r] / s : 0.f;   // size_factor shape (B,1)
    }
    __syncthreads();

    #pragma unroll
    for (int m = 0; m < MT; m++) {
        int r = s_row[m];
        if (r < 0) continue;
        float sc = s_scale[m];
        float4 o;
        o.x = v[m][0] * sc; o.y = v[m][1] * sc;
        o.z = v[m][2] * sc; o.w = v[m][3] * sc;
        *(float4*)(out + (size_t)r * NO + 4 * tid) = o;   // STG.128 coalesced
    }
}

extern "C" void kernel_launch(void* const* d_in, const int* in_sizes, int n_in,
                              void* d_out, int out_size) {
    const float* z         = (const float*)d_in[0];
    const float* sf        = (const float*)d_in[1];
    const float* amat_w    = (const float*)d_in[2];
    const float* amat_site = (const float*)d_in[3];
    const float* offsets   = (const float*)d_in[4];
    const float* px_r      = (const float*)d_in[5];
    float* out = (float*)d_out;

    kA_prep_wg<<<NWAVE + 1, 512>>>(z, amat_w, amat_site);
    kB_gemm_softmax<<<NB_B, K5T>>>(z, sf, offsets, px_r, out);
}